// round 2
// baseline (speedup 1.0000x reference)
#include <cuda_runtime.h>

// clip(x + noise, 0, 1) over 50,331,648 fp32 elements.
// Pure HBM stream: 604 MB traffic. R1: streaming cache hints (.cs) +
// 4x batched unroll (8 loads in flight before stores) to maximize MLP
// and avoid useless L2 allocation.

#define UNROLL 4

__global__ void __launch_bounds__(256)
gauss_noise_kernel(const float4* __restrict__ x,
                   const float4* __restrict__ n,
                   float4* __restrict__ out,
                   int nvec) {
    const int tid = blockIdx.x * blockDim.x + threadIdx.x;
    const int stride = gridDim.x * blockDim.x;

    // Main body: full UNROLL batches (grid sized so most threads take this path)
    int i = tid;
    const int batch_span = stride * UNROLL;
    for (; i + stride * (UNROLL - 1) < nvec; i += batch_span) {
        float4 a[UNROLL], b[UNROLL];
#pragma unroll
        for (int u = 0; u < UNROLL; u++) a[u] = __ldcs(&x[i + u * stride]);
#pragma unroll
        for (int u = 0; u < UNROLL; u++) b[u] = __ldcs(&n[i + u * stride]);
#pragma unroll
        for (int u = 0; u < UNROLL; u++) {
            float4 r;
            r.x = __saturatef(a[u].x + b[u].x);
            r.y = __saturatef(a[u].y + b[u].y);
            r.z = __saturatef(a[u].z + b[u].z);
            r.w = __saturatef(a[u].w + b[u].w);
            __stcs(&out[i + u * stride], r);
        }
    }
    // Tail
    for (; i < nvec; i += stride) {
        float4 a = __ldcs(&x[i]);
        float4 b = __ldcs(&n[i]);
        float4 r;
        r.x = __saturatef(a.x + b.x);
        r.y = __saturatef(a.y + b.y);
        r.z = __saturatef(a.z + b.z);
        r.w = __saturatef(a.w + b.w);
        __stcs(&out[i], r);
    }
}

extern "C" void kernel_launch(void* const* d_in, const int* in_sizes, int n_in,
                              void* d_out, int out_size) {
    const float4* x = (const float4*)d_in[0];
    const float4* n = (const float4*)d_in[1];
    float4* out = (float4*)d_out;

    int nvec = in_sizes[0] / 4;  // 12,582,912
    const int threads = 256;
    // 1.57M threads -> each thread: 8 float4 elements = 2 unroll-4 batches.
    // 6144 CTAs = 148 SMs fully occupied (91%+ occ measured).
    int blocks = 6144;
    gauss_noise_kernel<<<blocks, threads>>>(x, n, out, nvec);
}